// round 15
// baseline (speedup 1.0000x reference)
#include <cuda_runtime.h>
#include <cuda_bf16.h>
#include <mma.h>

using namespace nvcuda;

#define DIN 784
#define H   32
#define KC  32            /* two wmma k-steps per chunk */
#define NCH 25            /* 24*32 + 16 valid; last chunk zero-padded */
#define TM  64
#define NTH 64            /* 2 warps; warp w owns rows w*32..w*32+31 */
#define LDA 40            /* A bf16 tile ld: 80B rows */
#define LDB 40            /* B bf16 tile ld */
#define SHS 36            /* h f32 tile ld */

typedef unsigned int uint;

__device__ __forceinline__ float2 cmul(float2 a, float2 b){
    return make_float2(a.x*b.x - a.y*b.y, a.x*b.y + a.y*b.x);
}

// ---------------------------------------------------------------------------
// Single fused kernel: in-kernel W split + WMMA bf16 split-GEMM
// (D = XhWh + XhWl + XlWh, f32 acc) + per-block U build + epilogue.
// 64 threads, 64 rows; warp w owns rows w*32..w*32+31.
// One __syncthreads per chunk; no cp.async; register prefetch 1 chunk ahead.
// ---------------------------------------------------------------------------
__global__ void __launch_bounds__(NTH) fused_kernel(
    const float* __restrict__ x,   const float* __restrict__ w1,
    const float* __restrict__ b1,  const float* __restrict__ lng,
    const float* __restrict__ lnb, const float* __restrict__ w2,
    const float* __restrict__ b2,  const float* __restrict__ shared_w,
    const float* __restrict__ task_w,
    const float* __restrict__ pw,  const float* __restrict__ pb,
    float2* __restrict__ out)
{
    // sPool: A tiles (hi 5120B + lo 5120B) during GEMM; h tile (9216B) after.
    __shared__ __align__(16) char sPool[10240];
    __shared__ __align__(16) __nv_bfloat16 sB[2][2*KC*LDB];    // [buf][hi|lo] 10KB
    __shared__ __align__(16) float2 sU[256];                   // built in-kernel
    __shared__ float s_b1[H], s_g[H], s_b[H], s_w2[H*4], s_b2[4], s_pw[8], s_pb[2];

    __nv_bfloat16* sAh = (__nv_bfloat16*)sPool;                // 64*40
    __nv_bfloat16* sAl = (__nv_bfloat16*)(sPool + 5120);       // 64*40

    const int tid = threadIdx.x, w = tid >> 5, lane = tid & 31;
    const int row0 = blockIdx.x * TM;

    if (tid < H){ s_b1[tid]=b1[tid]; s_g[tid]=lng[tid]; s_b[tid]=lnb[tid]; }
    #pragma unroll
    for (int it = 0; it < 2; it++) s_w2[it*NTH + tid] = w2[it*NTH + tid];
    if (tid < 4) s_b2[tid] = b2[tid];
    if (tid < 8) s_pw[tid] = pw[tid];
    if (tid < 2) s_pb[tid] = pb[tid];

    // ---- x: direct coalesced LDG.128, register buffer (8 rows/lane-group) ----
    float4 xp[8];
    const float* xbase = x + (size_t)(row0 + w*32 + (lane>>3))*DIN + (lane&7)*4;
    auto ldgX = [&](int ch){
        const float* p = xbase + ch*KC;
        const bool zpad = (ch == NCH-1) && ((lane&7) >= 4);   // k >= 784
        #pragma unroll
        for (int it = 0; it < 8; it++)
            xp[it] = zpad ? make_float4(0.f,0.f,0.f,0.f)
                          : *(const float4*)(p + (size_t)it*4*DIN);
    };

    // ---- W: coalesced LDG.128 of the contiguous 4KB fp32 chunk ----
    float4 wp[4];
    auto ldgW = [&](int ch){
        const float* p = w1 + (size_t)ch*KC*H + tid*16;
        const bool valid = (ch < NCH-1) || (tid < 32);        // k < 784
        #pragma unroll
        for (int i = 0; i < 4; i++)
            wp[i] = valid ? *(const float4*)(p + i*4)
                          : make_float4(0.f,0.f,0.f,0.f);
    };

    const uint acol  = (lane & 7) * 4;            // bf16 col within A row
    const uint arow0 = w*32 + (lane >> 3);

    // convert xp -> A tiles (own 32 rows)
    auto convX = [&](){
        #pragma unroll
        for (int it = 0; it < 8; it++){
            const float* f = (const float*)&xp[it];
            __nv_bfloat162 a0 = __float22bfloat162_rn(make_float2(f[0], f[1]));
            __nv_bfloat162 a1 = __float22bfloat162_rn(make_float2(f[2], f[3]));
            __nv_bfloat162 c0 = __float22bfloat162_rn(make_float2(
                f[0]-__bfloat162float(a0.x), f[1]-__bfloat162float(a0.y)));
            __nv_bfloat162 c1 = __float22bfloat162_rn(make_float2(
                f[2]-__bfloat162float(a1.x), f[3]-__bfloat162float(a1.y)));
            uint r = arow0 + it*4;
            *(uint2*)(sAh + r*LDA + acol) = make_uint2(*(uint*)&a0, *(uint*)&a1);
            *(uint2*)(sAl + r*LDA + acol) = make_uint2(*(uint*)&c0, *(uint*)&c1);
        }
    };

    // convert wp -> B tiles in sB[buf]: thread t = k-row t>>1, col-half (t&1)*16
    const uint wrow = tid >> 1, wcol = (tid & 1) * 16;
    auto convW = [&](int buf){
        __nv_bfloat16* bh = &sB[buf][0];
        __nv_bfloat16* bl = &sB[buf][KC*LDB];
        #pragma unroll
        for (int i = 0; i < 4; i++){
            const float* f = (const float*)&wp[i];
            __nv_bfloat162 a0 = __float22bfloat162_rn(make_float2(f[0], f[1]));
            __nv_bfloat162 a1 = __float22bfloat162_rn(make_float2(f[2], f[3]));
            __nv_bfloat162 c0 = __float22bfloat162_rn(make_float2(
                f[0]-__bfloat162float(a0.x), f[1]-__bfloat162float(a0.y)));
            __nv_bfloat162 c1 = __float22bfloat162_rn(make_float2(
                f[2]-__bfloat162float(a1.x), f[3]-__bfloat162float(a1.y)));
            uint off = wrow*LDB + wcol + i*4;
            *(uint2*)(bh + off) = make_uint2(*(uint*)&a0, *(uint*)&a1);
            *(uint2*)(bl + off) = make_uint2(*(uint*)&c0, *(uint*)&c1);
        }
    };

    wmma::fragment<wmma::accumulator, 16,16,16, float> acc[2][2];
    #pragma unroll
    for (int mt = 0; mt < 2; mt++)
        #pragma unroll
        for (int nt = 0; nt < 2; nt++) wmma::fill_fragment(acc[mt][nt], 0.f);

    // ---- pre-loop: chunk 0 into tiles, chunk 1 into regs ----
    ldgX(0); ldgW(0);
    convX(); convW(0);
    ldgX(1); ldgW(1);
    __syncthreads();          // tiles(0) + params visible

    #pragma unroll 1
    for (int ch = 0; ch < NCH; ch++){
        const int buf = ch & 1;

        // --- fragments + 12 WMMA (consume tiles ch) ---
        const __nv_bfloat16* bBase = &sB[buf][0];
        #pragma unroll
        for (int ks = 0; ks < 2; ks++){
            wmma::fragment<wmma::matrix_a, 16,16,16, __nv_bfloat16, wmma::row_major> ah[2], al[2];
            wmma::fragment<wmma::matrix_b, 16,16,16, __nv_bfloat16, wmma::row_major> bh[2], bl[2];
            #pragma unroll
            for (int mt = 0; mt < 2; mt++){
                wmma::load_matrix_sync(ah[mt], sAh + (w*32 + mt*16)*LDA + ks*16, LDA);
                wmma::load_matrix_sync(al[mt], sAl + (w*32 + mt*16)*LDA + ks*16, LDA);
            }
            #pragma unroll
            for (int nt = 0; nt < 2; nt++){
                wmma::load_matrix_sync(bh[nt], bBase + ks*16*LDB + nt*16,          LDB);
                wmma::load_matrix_sync(bl[nt], bBase + KC*LDB + ks*16*LDB + nt*16, LDB);
            }
            #pragma unroll
            for (int mt = 0; mt < 2; mt++)
                #pragma unroll
                for (int nt = 0; nt < 2; nt++){
                    wmma::mma_sync(acc[mt][nt], ah[mt], bh[nt], acc[mt][nt]);
                    wmma::mma_sync(acc[mt][nt], ah[mt], bl[nt], acc[mt][nt]);
                    wmma::mma_sync(acc[mt][nt], al[mt], bh[nt], acc[mt][nt]);
                }
        }

        // --- produce tiles for ch+1 (A: warp-local; B: other buffer) ---
        if (ch + 1 < NCH){
            convX();                 // xp holds x(ch+1)
            convW(buf ^ 1);          // wp holds w(ch+1)
        }
        if (ch + 2 < NCH){ ldgX(ch + 2); ldgW(ch + 2); }

        __syncthreads();             // STS(ch+1) visible to both warps
    }

    // ---- warp 0 builds the 16x16 unitary U into sU (warp-scope sync) ----
    if (tid < 32){
        for (int i = tid; i < 256; i += 32)
            sU[i] = make_float2((i>>4)==(i&15) ? 1.f : 0.f, 0.f);
        __syncwarp();
        for (int l = 0; l < 3; l++){
            const float* wpar = (l < 2) ? (shared_w + l*12) : task_w;
            for (int wire = 0; wire < 4; wire++){
                float phi = wpar[wire*3+0], th = wpar[wire*3+1], om = wpar[wire*3+2];
                float chh = cosf(0.5f*th), shn = sinf(0.5f*th);
                float a = 0.5f*(phi+om), d = 0.5f*(phi-om);
                float sa, ca, sd, cd;
                sincosf(a, &sa, &ca); sincosf(d, &sd, &cd);
                float2 m00 = make_float2( ca*chh, -sa*chh);
                float2 m01 = make_float2(-cd*shn, -sd*shn);
                float2 m10 = make_float2( cd*shn, -sd*shn);
                float2 m11 = make_float2( ca*chh,  sa*chh);
                int bp = 3 - wire;
                for (int t = tid; t < 128; t += 32){
                    int p = t >> 4, col = t & 15;
                    int r0 = ((p >> bp) << (bp+1)) | (p & ((1<<bp)-1));
                    int r1 = r0 | (1 << bp);
                    float2 u0 = sU[r0*16+col], u1 = sU[r1*16+col];
                    float2 t0 = cmul(m00,u0), t1 = cmul(m01,u1);
                    float2 t2 = cmul(m10,u0), t3 = cmul(m11,u1);
                    sU[r0*16+col] = make_float2(t0.x+t1.x, t0.y+t1.y);
                    sU[r1*16+col] = make_float2(t2.x+t3.x, t2.y+t3.y);
                }
                __syncwarp();
            }
            int r = (l == 1) ? 2 : 1;
            for (int i = 0; i < 4; i++){
                int c = i, t = (i + r) & 3;
                int pc = 3 - c, pt = 3 - t;
                for (int tk = tid; tk < 64; tk += 32){
                    int idx = tk >> 4, col = tk & 15;
                    int rem0 = -1, rem1 = -1;
                    for (int bit = 3; bit >= 0; bit--)
                        if (bit != pc && bit != pt){ if (rem0 < 0) rem0 = bit; else rem1 = bit; }
                    int b  = (1 << pc) | (((idx>>1)&1) << rem0) | ((idx&1) << rem1);
                    int b2 = b | (1 << pt);
                    float2 tmp = sU[b*16+col];
                    sU[b*16+col] = sU[b2*16+col];
                    sU[b2*16+col] = tmp;
                }
                __syncwarp();
            }
        }
    }

    // ---- h tile into sPool (overwrites A tiles) ----
    float* sh = (float*)sPool;            // 64*36*4 = 9216 <= 10240
    #pragma unroll
    for (int mt = 0; mt < 2; mt++)
        #pragma unroll
        for (int nt = 0; nt < 2; nt++)
            wmma::store_matrix_sync(&sh[(w*32 + mt*16)*SHS + nt*16],
                                    acc[mt][nt], SHS, wmma::mem_row_major);
    __syncthreads();   // sU (warp 0) + h rows visible to all

    // ---- per-row epilogue: thread tid = row tid ----
    {
        float h[32];
        const float4* hr = (const float4*)&sh[tid*SHS];
        #pragma unroll
        for (int q = 0; q < 8; q++){
            float4 v = hr[q];
            float v0 = v.x + s_b1[q*4],   v1 = v.y + s_b1[q*4+1];
            float v2 = v.z + s_b1[q*4+2], v3 = v.w + s_b1[q*4+3];
            h[q*4]   = v0 > 0.f ? v0 : 0.f;
            h[q*4+1] = v1 > 0.f ? v1 : 0.f;
            h[q*4+2] = v2 > 0.f ? v2 : 0.f;
            h[q*4+3] = v3 > 0.f ? v3 : 0.f;
        }
        float mu = 0.f;
        #pragma unroll
        for (int c = 0; c < 32; c++) mu += h[c];
        mu *= (1.f/32.f);
        float var = 0.f;
        #pragma unroll
        for (int c = 0; c < 32; c++){ float d = h[c]-mu; var += d*d; }
        var *= (1.f/32.f);
        float inv = rsqrtf(var + 1e-5f);

        float z0 = s_b2[0], z1 = s_b2[1], z2 = s_b2[2], z3 = s_b2[3];
        #pragma unroll
        for (int c = 0; c < 32; c++){
            float hn = (h[c]-mu)*inv*s_g[c] + s_b[c];
            z0 += hn * s_w2[c*4+0];
            z1 += hn * s_w2[c*4+1];
            z2 += hn * s_w2[c*4+2];
            z3 += hn * s_w2[c*4+3];
        }
        float cs[4], sn[4], zz;
        zz = tanhf(z0) * 1.5707963267948966f; sincosf(zz, &sn[0], &cs[0]);
        zz = tanhf(z1) * 1.5707963267948966f; sincosf(zz, &sn[1], &cs[1]);
        zz = tanhf(z2) * 1.5707963267948966f; sincosf(zz, &sn[2], &cs[2]);
        zz = tanhf(z3) * 1.5707963267948966f; sincosf(zz, &sn[3], &cs[3]);

        float t01[4], t23[4], psi[16];
        t01[0]=cs[0]*cs[1]; t01[1]=cs[0]*sn[1]; t01[2]=sn[0]*cs[1]; t01[3]=sn[0]*sn[1];
        t23[0]=cs[2]*cs[3]; t23[1]=cs[2]*sn[3]; t23[2]=sn[2]*cs[3]; t23[3]=sn[2]*sn[3];
        #pragma unroll
        for (int bb = 0; bb < 16; bb++) psi[bb] = t01[bb>>2]*t23[bb&3];

        float e0=0.f, e1=0.f, e2=0.f, e3=0.f;
        #pragma unroll 4
        for (int j = 0; j < 16; j++){
            float re = 0.f, im = 0.f;
            #pragma unroll
            for (int bb = 0; bb < 16; bb++){
                float2 u = sU[j*16 + bb];
                re += psi[bb]*u.x;
                im += psi[bb]*u.y;
            }
            float p = re*re + im*im;
            e0 += (j & 8) ? -p : p;
            e1 += (j & 4) ? -p : p;
            e2 += (j & 2) ? -p : p;
            e3 += (j & 1) ? -p : p;
        }
        float o0 = s_pb[0] + e0*s_pw[0] + e1*s_pw[2] + e2*s_pw[4] + e3*s_pw[6];
        float o1 = s_pb[1] + e0*s_pw[1] + e1*s_pw[3] + e2*s_pw[5] + e3*s_pw[7];
        out[row0 + tid] = make_float2(o0, o1);
    }
}

// ---------------------------------------------------------------------------
extern "C" void kernel_launch(void* const* d_in, const int* in_sizes, int n_in,
                              void* d_out, int out_size)
{
    const float* x   = (const float*)d_in[0];
    const float* w1  = (const float*)d_in[1];
    const float* b1  = (const float*)d_in[2];
    const float* lng = (const float*)d_in[3];
    const float* lnb = (const float*)d_in[4];
    const float* w2  = (const float*)d_in[5];
    const float* b2  = (const float*)d_in[6];
    const float* sw  = (const float*)d_in[7];
    const float* tw  = (const float*)d_in[8];
    const float* pw  = (const float*)d_in[9];
    const float* pb  = (const float*)d_in[10];
    (void)n_in; (void)out_size;

    int rows = in_sizes[0] / DIN;

    fused_kernel<<<rows / TM, NTH>>>(x, w1, b1, lng, lnb, w2, b2, sw, tw,
                                     pw, pb, (float2*)d_out);
}

// round 17
// speedup vs baseline: 1.1509x; 1.1509x over previous
#include <cuda_runtime.h>
#include <cuda_bf16.h>
#include <mma.h>

using namespace nvcuda;

#define DIN 784
#define H   32
#define KC  32            /* two wmma k-steps per chunk */
#define NCH 25            /* 24*32 + 16 valid; last chunk zero-padded */
#define TM  64
#define NTH 64            /* 2 warps; warp w owns rows w*32..w*32+31 */
#define LDA 40            /* A bf16 tile ld: 80B rows */
#define LDB 40            /* B bf16 tile ld */
#define SHS 36            /* h f32 tile ld */

typedef unsigned int uint;

__device__ __align__(16) __nv_bfloat16 g_b[NCH*2*KC*LDB];     // [ch][hi|lo][32*40]

__device__ __forceinline__ uint smem_u32(const void* p){
    uint a; asm("{ .reg .u64 t; cvta.to.shared.u64 t, %1; cvt.u32.u64 %0, t; }"
                : "=r"(a) : "l"(p));
    return a;
}
__device__ __forceinline__ void cp16(void* dst, const void* src){
    uint d = smem_u32(dst);
    asm volatile("cp.async.cg.shared.global [%0], [%1], 16;" :: "r"(d), "l"(src));
}
__device__ __forceinline__ float2 cmul(float2 a, float2 b){
    return make_float2(a.x*b.x - a.y*b.y, a.x*b.y + a.y*b.x);
}

// ---------------------------------------------------------------------------
// Prologue: W-split ONLY (pure streaming). U-build moved into fused kernel.
// ---------------------------------------------------------------------------
__global__ void prep_w_kernel(const float* __restrict__ w1){
    int idx = blockIdx.x*128 + threadIdx.x;
    int stride = gridDim.x*128;
    const int TOT = NCH*KC*LDB;
    for (; idx < TOT; idx += stride){
        int ch = idx / (KC*LDB);
        int r  = (idx % (KC*LDB)) / LDB;
        int c  = idx % LDB;
        int k  = ch*KC + r;
        float v = (c < H && k < DIN) ? w1[k*H + c] : 0.f;
        __nv_bfloat16 hb = __float2bfloat16(v);
        __nv_bfloat16 lb = __float2bfloat16(v - __bfloat162float(hb));
        g_b[(ch*2 + 0)*(KC*LDB) + r*LDB + c] = hb;
        g_b[(ch*2 + 1)*(KC*LDB) + r*LDB + c] = lb;
    }
}

// ---------------------------------------------------------------------------
// Fused kernel: WMMA bf16 split-GEMM (D = XhWh + XhWl + XlWh, f32 acc)
// + in-kernel U build + LN/tanh/product-state/U-matvec/head.
// GEMM loop structure identical to the proven round-13 kernel.
// ---------------------------------------------------------------------------
__global__ void __launch_bounds__(NTH) fused_kernel(
    const float* __restrict__ x,   const float* __restrict__ b1,
    const float* __restrict__ lng, const float* __restrict__ lnb,
    const float* __restrict__ w2,  const float* __restrict__ b2,
    const float* __restrict__ shared_w, const float* __restrict__ task_w,
    const float* __restrict__ pw,  const float* __restrict__ pb,
    float2* __restrict__ out)
{
    // sPool: A tiles (hi 5120B + lo 5120B) during GEMM; h tile (9216B) after.
    __shared__ __align__(16) char sPool[10240];
    __shared__ __align__(16) __nv_bfloat16 sB[2][2*KC*LDB];    // [buf][hi|lo] 10KB
    __shared__ __align__(16) float2 sU[256];
    __shared__ float s_b1[H], s_g[H], s_b[H], s_w2[H*4], s_b2[4], s_pw[8], s_pb[2];

    __nv_bfloat16* sAh = (__nv_bfloat16*)sPool;                // 64*40
    __nv_bfloat16* sAl = (__nv_bfloat16*)(sPool + 5120);       // 64*40

    const int tid = threadIdx.x, w = tid >> 5, lane = tid & 31;
    const int row0 = blockIdx.x * TM;

    if (tid < H){ s_b1[tid]=b1[tid]; s_g[tid]=lng[tid]; s_b[tid]=lnb[tid]; }
    #pragma unroll
    for (int it = 0; it < 2; it++) s_w2[it*NTH + tid] = w2[it*NTH + tid];
    if (tid < 4) s_b2[tid] = b2[tid];
    if (tid < 8) s_pw[tid] = pw[tid];
    if (tid < 2) s_pb[tid] = pb[tid];

    // ---- B staging: cp.async double buffer (5120B = 320 x 16B per chunk) ----
    auto stageB = [&](int ch, int buf){
        const char* srcB = (const char*)g_b + (size_t)ch*5120;
        char* dstB = (char*)&sB[buf][0];
        #pragma unroll
        for (int it = 0; it < 5; it++)
            cp16(dstB + (it*NTH + tid)*16, srcB + (it*NTH + tid)*16);
        asm volatile("cp.async.commit_group;");
    };

    // ---- x: direct coalesced LDG.128, register buffer (8 rows/lane-group) ----
    float4 xp[8];
    const float* xbase = x + (size_t)(row0 + w*32 + (lane>>3))*DIN + (lane&7)*4;
    auto ldgX = [&](int ch){
        const float* p = xbase + ch*KC;
        const bool zpad = (ch == NCH-1) && ((lane&7) >= 4);   // k >= 784
        #pragma unroll
        for (int it = 0; it < 8; it++)
            xp[it] = zpad ? make_float4(0.f,0.f,0.f,0.f)
                          : *(const float4*)(p + (size_t)it*4*DIN);
    };

    wmma::fragment<wmma::accumulator, 16,16,16, float> acc[2][2];
    #pragma unroll
    for (int mt = 0; mt < 2; mt++)
        #pragma unroll
        for (int nt = 0; nt < 2; nt++) wmma::fill_fragment(acc[mt][nt], 0.f);

    stageB(0, 0);
    stageB(1, 1);
    ldgX(0);

    const uint acol  = (lane & 7) * 4;            // bf16 col within A row
    const uint arow0 = w*32 + (lane >> 3);

    #pragma unroll 1
    for (int ch = 0; ch < NCH; ch++){
        const int buf = ch & 1;

        // --- convert regs -> bf16 hi/lo, STS.64 into A tiles (own 32 rows) ---
        #pragma unroll
        for (int it = 0; it < 8; it++){
            const float* f = (const float*)&xp[it];
            __nv_bfloat162 a0 = __float22bfloat162_rn(make_float2(f[0], f[1]));
            __nv_bfloat162 a1 = __float22bfloat162_rn(make_float2(f[2], f[3]));
            __nv_bfloat162 c0 = __float22bfloat162_rn(make_float2(
                f[0]-__bfloat162float(a0.x), f[1]-__bfloat162float(a0.y)));
            __nv_bfloat162 c1 = __float22bfloat162_rn(make_float2(
                f[2]-__bfloat162float(a1.x), f[3]-__bfloat162float(a1.y)));
            uint r = arow0 + it*4;
            *(uint2*)(sAh + r*LDA + acol) = make_uint2(*(uint*)&a0, *(uint*)&a1);
            *(uint2*)(sAl + r*LDA + acol) = make_uint2(*(uint*)&c0, *(uint*)&c1);
        }

        if (ch + 1 < NCH) ldgX(ch + 1);           // prefetch next chunk's x

        asm volatile("cp.async.wait_group 1;");   // B(ch) landed
        __syncthreads();                           // B + A tiles visible

        // --- 2 k-steps x (frag loads + 12 WMMA) ---
        const __nv_bfloat16* bBase = &sB[buf][0];
        #pragma unroll
        for (int ks = 0; ks < 2; ks++){
            wmma::fragment<wmma::matrix_a, 16,16,16, __nv_bfloat16, wmma::row_major> ah[2], al[2];
            wmma::fragment<wmma::matrix_b, 16,16,16, __nv_bfloat16, wmma::row_major> bh[2], bl[2];
            #pragma unroll
            for (int mt = 0; mt < 2; mt++){
                wmma::load_matrix_sync(ah[mt], sAh + (w*32 + mt*16)*LDA + ks*16, LDA);
                wmma::load_matrix_sync(al[mt], sAl + (w*32 + mt*16)*LDA + ks*16, LDA);
            }
            #pragma unroll
            for (int nt = 0; nt < 2; nt++){
                wmma::load_matrix_sync(bh[nt], bBase + ks*16*LDB + nt*16,          LDB);
                wmma::load_matrix_sync(bl[nt], bBase + KC*LDB + ks*16*LDB + nt*16, LDB);
            }
            #pragma unroll
            for (int mt = 0; mt < 2; mt++)
                #pragma unroll
                for (int nt = 0; nt < 2; nt++){
                    wmma::mma_sync(acc[mt][nt], ah[mt], bh[nt], acc[mt][nt]);
                    wmma::mma_sync(acc[mt][nt], ah[mt], bl[nt], acc[mt][nt]);
                    wmma::mma_sync(acc[mt][nt], al[mt], bh[nt], acc[mt][nt]);
                }
        }

        __syncthreads();                  // B buf + A tiles consumed
        if (ch + 2 < NCH) stageB(ch + 2, buf);
        else asm volatile("cp.async.commit_group;");   // keep FIFO accounting
    }

    asm volatile("cp.async.wait_group 0;");

    // ---- warp 0 builds the 16x16 unitary U into sU (proven in round 15) ----
    if (tid < 32){
        for (int i = tid; i < 256; i += 32)
            sU[i] = make_float2((i>>4)==(i&15) ? 1.f : 0.f, 0.f);
        __syncwarp();
        for (int l = 0; l < 3; l++){
            const float* wpar = (l < 2) ? (shared_w + l*12) : task_w;
            for (int wire = 0; wire < 4; wire++){
                float phi = wpar[wire*3+0], th = wpar[wire*3+1], om = wpar[wire*3+2];
                float chh = cosf(0.5f*th), shn = sinf(0.5f*th);
                float a = 0.5f*(phi+om), d = 0.5f*(phi-om);
                float sa, ca, sd, cd;
                sincosf(a, &sa, &ca); sincosf(d, &sd, &cd);
                float2 m00 = make_float2( ca*chh, -sa*chh);
                float2 m01 = make_float2(-cd*shn, -sd*shn);
                float2 m10 = make_float2( cd*shn, -sd*shn);
                float2 m11 = make_float2( ca*chh,  sa*chh);
                int bp = 3 - wire;
                for (int t = tid; t < 128; t += 32){
                    int p = t >> 4, col = t & 15;
                    int r0 = ((p >> bp) << (bp+1)) | (p & ((1<<bp)-1));
                    int r1 = r0 | (1 << bp);
                    float2 u0 = sU[r0*16+col], u1 = sU[r1*16+col];
                    float2 t0 = cmul(m00,u0), t1 = cmul(m01,u1);
                    float2 t2 = cmul(m10,u0), t3 = cmul(m11,u1);
                    sU[r0*16+col] = make_float2(t0.x+t1.x, t0.y+t1.y);
                    sU[r1*16+col] = make_float2(t2.x+t3.x, t2.y+t3.y);
                }
                __syncwarp();
            }
            int r = (l == 1) ? 2 : 1;
            for (int i = 0; i < 4; i++){
                int c = i, t = (i + r) & 3;
                int pc = 3 - c, pt = 3 - t;
                for (int tk = tid; tk < 64; tk += 32){
                    int idx = tk >> 4, col = tk & 15;
                    int rem0 = -1, rem1 = -1;
                    for (int bit = 3; bit >= 0; bit--)
                        if (bit != pc && bit != pt){ if (rem0 < 0) rem0 = bit; else rem1 = bit; }
                    int b  = (1 << pc) | (((idx>>1)&1) << rem0) | ((idx&1) << rem1);
                    int b2 = b | (1 << pt);
                    float2 tmp = sU[b*16+col];
                    sU[b*16+col] = sU[b2*16+col];
                    sU[b2*16+col] = tmp;
                }
                __syncwarp();
            }
        }
    }

    // ---- h tile into sPool (overwrites A tiles; last MMA fenced by the
    //      loop-final __syncthreads) ----
    float* sh = (float*)sPool;            // 64*36*4 = 9216 <= 10240
    #pragma unroll
    for (int mt = 0; mt < 2; mt++)
        #pragma unroll
        for (int nt = 0; nt < 2; nt++)
            wmma::store_matrix_sync(&sh[(w*32 + mt*16)*SHS + nt*16],
                                    acc[mt][nt], SHS, wmma::mem_row_major);
    __syncthreads();   // publish sU (warp 0) + h rows to all threads

    // ---- per-row epilogue: thread tid = row tid ----
    {
        float h[32];
        const float4* hr = (const float4*)&sh[tid*SHS];
        #pragma unroll
        for (int q = 0; q < 8; q++){
            float4 v = hr[q];
            float v0 = v.x + s_b1[q*4],   v1 = v.y + s_b1[q*4+1];
            float v2 = v.z + s_b1[q*4+2], v3 = v.w + s_b1[q*4+3];
            h[q*4]   = v0 > 0.f ? v0 : 0.f;
            h[q*4+1] = v1 > 0.f ? v1 : 0.f;
            h[q*4+2] = v2 > 0.f ? v2 : 0.f;
            h[q*4+3] = v3 > 0.f ? v3 : 0.f;
        }
        float mu = 0.f;
        #pragma unroll
        for (int c = 0; c < 32; c++) mu += h[c];
        mu *= (1.f/32.f);
        float var = 0.f;
        #pragma unroll
        for (int c = 0; c < 32; c++){ float d = h[c]-mu; var += d*d; }
        var *= (1.f/32.f);
        float inv = rsqrtf(var + 1e-5f);

        float z0 = s_b2[0], z1 = s_b2[1], z2 = s_b2[2], z3 = s_b2[3];
        #pragma unroll
        for (int c = 0; c < 32; c++){
            float hn = (h[c]-mu)*inv*s_g[c] + s_b[c];
            z0 += hn * s_w2[c*4+0];
            z1 += hn * s_w2[c*4+1];
            z2 += hn * s_w2[c*4+2];
            z3 += hn * s_w2[c*4+3];
        }
        float cs[4], sn[4], zz;
        zz = tanhf(z0) * 1.5707963267948966f; sincosf(zz, &sn[0], &cs[0]);
        zz = tanhf(z1) * 1.5707963267948966f; sincosf(zz, &sn[1], &cs[1]);
        zz = tanhf(z2) * 1.5707963267948966f; sincosf(zz, &sn[2], &cs[2]);
        zz = tanhf(z3) * 1.5707963267948966f; sincosf(zz, &sn[3], &cs[3]);

        float t01[4], t23[4], psi[16];
        t01[0]=cs[0]*cs[1]; t01[1]=cs[0]*sn[1]; t01[2]=sn[0]*cs[1]; t01[3]=sn[0]*sn[1];
        t23[0]=cs[2]*cs[3]; t23[1]=cs[2]*sn[3]; t23[2]=sn[2]*cs[3]; t23[3]=sn[2]*sn[3];
        #pragma unroll
        for (int bb = 0; bb < 16; bb++) psi[bb] = t01[bb>>2]*t23[bb&3];

        float e0=0.f, e1=0.f, e2=0.f, e3=0.f;
        #pragma unroll 4
        for (int j = 0; j < 16; j++){
            float re = 0.f, im = 0.f;
            #pragma unroll
            for (int bb = 0; bb < 16; bb++){
                float2 u = sU[j*16 + bb];
                re += psi[bb]*u.x;
                im += psi[bb]*u.y;
            }
            float p = re*re + im*im;
            e0 += (j & 8) ? -p : p;
            e1 += (j & 4) ? -p : p;
            e2 += (j & 2) ? -p : p;
            e3 += (j & 1) ? -p : p;
        }
        float o0 = s_pb[0] + e0*s_pw[0] + e1*s_pw[2] + e2*s_pw[4] + e3*s_pw[6];
        float o1 = s_pb[1] + e0*s_pw[1] + e1*s_pw[3] + e2*s_pw[5] + e3*s_pw[7];
        out[row0 + tid] = make_float2(o0, o1);
    }
}

// ---------------------------------------------------------------------------
extern "C" void kernel_launch(void* const* d_in, const int* in_sizes, int n_in,
                              void* d_out, int out_size)
{
    const float* x   = (const float*)d_in[0];
    const float* w1  = (const float*)d_in[1];
    const float* b1  = (const float*)d_in[2];
    const float* lng = (const float*)d_in[3];
    const float* lnb = (const float*)d_in[4];
    const float* w2  = (const float*)d_in[5];
    const float* b2  = (const float*)d_in[6];
    const float* sw  = (const float*)d_in[7];
    const float* tw  = (const float*)d_in[8];
    const float* pw  = (const float*)d_in[9];
    const float* pb  = (const float*)d_in[10];
    (void)n_in; (void)out_size;

    int rows = in_sizes[0] / DIN;

    prep_w_kernel<<<132, 128>>>(w1);
    fused_kernel<<<rows / TM, NTH>>>(x, b1, lng, lnb, w2, b2, sw, tw,
                                     pw, pb, (float2*)d_out);
}